// round 13
// baseline (speedup 1.0000x reference)
#include <cuda_runtime.h>
#include <cuda_fp16.h>
#include <cstdint>
#include <cstddef>

#define DEVI __device__ __forceinline__
typedef __half f16;

constexpr int Bsz = 8192, Csz = 256, NBl = 8;
constexpr size_t BC = (size_t)Bsz * Csz;   // elems per blade plane

// ---------------- scratch (device globals) ----------------
__device__ f16 g_rawH[NBl * BC], g_rawL[NBl * BC];
__device__ f16 g_xrH [NBl * BC], g_xrL [NBl * BC];
__device__ f16 g_lfH [NBl * BC], g_lfL [NBl * BC];
__device__ f16 g_hH  [NBl * BC], g_hL  [NBl * BC];
__device__ f16 g_inH [NBl * BC];
__device__ f16 g_wH  [4 * Csz * Csz], g_wL[4 * Csz * Csz];

// ---------------- algebra tables ----------------
__device__ constexpr int ORD [8] = {0, 1, 2, 4, 3, 5, 6, 7};
__device__ constexpr int IDXM[8] = {0, 1, 2, 4, 3, 5, 6, 7};
__device__ constexpr int GRc [8] = {0, 1, 1, 1, 2, 2, 2, 3};
__device__ constexpr unsigned NEGM[8] = {0x00u, 0x00u, 0xAAu, 0xAAu,
                                         0x66u, 0x66u, 0xCCu, 0xCCu};
__device__ constexpr signed char PATHT[4][4][4] = {
  { { 0,-1,-1,-1}, {-1, 1,-1,-1}, {-1,-1, 2,-1}, {-1,-1,-1, 3} },
  { {-1, 4,-1,-1}, { 5,-1, 6,-1}, {-1, 7,-1, 8}, {-1,-1, 9,-1} },
  { {-1,-1,10,-1}, {-1,11,-1,12}, {13,-1,14,-1}, {-1,15,-1,-1} },
  { {-1,-1,-1,16}, {-1,-1,17,-1}, {-1,18,-1,-1}, {19,-1,-1,-1} }
};

DEVI float sigm(float x) { return 1.0f / (1.0f + __expf(-x)); }

DEVI uint32_t smem_u32(const void* p) {
    uint32_t a;
    asm("{ .reg .u64 t; cvta.to.shared.u64 t, %1; cvt.u32.u64 %0, t; }" : "=r"(a) : "l"(p));
    return a;
}

// ---- warp MMA primitives ----
DEVI void ldsm_x4(uint32_t& r0, uint32_t& r1, uint32_t& r2, uint32_t& r3, uint32_t addr) {
    asm volatile("ldmatrix.sync.aligned.m8n8.x4.shared.b16 {%0,%1,%2,%3}, [%4];"
                 : "=r"(r0), "=r"(r1), "=r"(r2), "=r"(r3) : "r"(addr));
}
DEVI void mma_f16(float* c, uint32_t a0, uint32_t a1, uint32_t a2, uint32_t a3,
                  uint32_t b0, uint32_t b1) {
    asm volatile(
        "mma.sync.aligned.m16n8k16.row.col.f32.f16.f16.f32 "
        "{%0,%1,%2,%3}, {%4,%5,%6,%7}, {%8,%9}, {%0,%1,%2,%3};"
        : "+f"(c[0]), "+f"(c[1]), "+f"(c[2]), "+f"(c[3])
        : "r"(a0), "r"(a1), "r"(a2), "r"(a3), "r"(b0), "r"(b1));
}
DEVI void cpa16(uint32_t dst, const void* src) {
    asm volatile("cp.async.cg.shared.global [%0], [%1], 16;" :: "r"(dst), "l"(src));
}
#define CPA_COMMIT()  asm volatile("cp.async.commit_group;" ::: "memory")
#define CPA_WAIT(n)   asm volatile("cp.async.wait_group %0;" :: "n"(n) : "memory")

// ---------------- mma.sync blade-plane GEMM (fp16 2-term, cp.async 2-stage) ----------------
constexpr int SKW = 40;
constexpr int ARR = 128 * SKW;
constexpr int STG = 3 * ARR;               // A, WH, WL per stage
constexpr int GEMM_SMEM = 2 * STG * (int)sizeof(f16);   // 61440 B

__global__ void __launch_bounds__(256, 2)
gemm_mma(const f16* __restrict__ A, const f16* __restrict__ WH,
         const f16* __restrict__ WL, f16* __restrict__ OH, f16* __restrict__ OL)
{
    extern __shared__ f16 smem[];
    const uint32_t sb = smem_u32(smem);

    const int tid = threadIdx.x, wid = tid >> 5, lane = tid & 31;
    const int blade = blockIdx.z, grade = GRc[blade];
    const int row0 = blockIdx.x * 128, col0 = blockIdx.y * 128;
    const int wm = wid & 1, wn = wid >> 1;

    const f16* aP  = A  + (size_t)blade * BC + (size_t)row0 * Csz;
    const f16* wHp = WH + (size_t)grade * Csz * Csz + (size_t)col0 * Csz;
    const f16* wLp = WL + (size_t)grade * Csz * Csz + (size_t)col0 * Csz;

    float acc[4][4][4];
#pragma unroll
    for (int mi = 0; mi < 4; mi++)
#pragma unroll
        for (int ni = 0; ni < 4; ni++)
#pragma unroll
            for (int q = 0; q < 4; q++) acc[mi][ni][q] = 0.0f;

    const int lq = lane >> 3, lr = lane & 7;
    const uint32_t offA = (uint32_t)(((lq & 1) * 8 + lr) * SKW + (lq >> 1) * 8) * 2;
    const uint32_t offB = (uint32_t)(((lq >> 1) * 8 + lr) * SKW + (lq & 1) * 8) * 2;

    auto load_chunk = [&](int ch, int s) {
        const uint32_t base = sb + (uint32_t)(s * STG) * 2;
#pragma unroll
        for (int it = 0; it < 2; it++) {
            const int t = tid + it * 256;
            const int r = t >> 2, c = t & 3;
            const size_t src = (size_t)r * Csz + ch * 32 + c * 8;
            const uint32_t d = (uint32_t)(r * SKW + c * 8) * 2;
            cpa16(base + 0 * ARR * 2 + d, aP  + src);
            cpa16(base + 1 * ARR * 2 + d, wHp + src);
            cpa16(base + 2 * ARR * 2 + d, wLp + src);
        }
        CPA_COMMIT();
    };

    load_chunk(0, 0);

    for (int ch = 0; ch < 8; ch++) {
        const int s = ch & 1;
        if (ch + 1 < 8) { load_chunk(ch + 1, (ch + 1) & 1); CPA_WAIT(1); }
        else            { CPA_WAIT(0); }
        __syncthreads();

        const uint32_t bA  = sb + (uint32_t)(s * STG + 0 * ARR) * 2;
        const uint32_t bBH = sb + (uint32_t)(s * STG + 1 * ARR) * 2;
        const uint32_t bBL = sb + (uint32_t)(s * STG + 2 * ARR) * 2;

#pragma unroll
        for (int kh = 0; kh < 2; kh++) {
            const uint32_t kb = (uint32_t)(kh * 16) * 2;
            uint32_t bh[4][2], bl[4][2];
#pragma unroll
            for (int nb = 0; nb < 2; nb++) {
                const uint32_t nbase = (uint32_t)((wn * 32 + nb * 16) * SKW) * 2;
                ldsm_x4(bh[nb*2][0], bh[nb*2][1], bh[nb*2+1][0], bh[nb*2+1][1],
                        bBH + nbase + offB + kb);
                ldsm_x4(bl[nb*2][0], bl[nb*2][1], bl[nb*2+1][0], bl[nb*2+1][1],
                        bBL + nbase + offB + kb);
            }
#pragma unroll
            for (int mi = 0; mi < 4; mi++) {
                const uint32_t mbase = (uint32_t)((wm * 64 + mi * 16) * SKW) * 2;
                uint32_t a0, a1, a2, a3;
                ldsm_x4(a0, a1, a2, a3, bA + mbase + offA + kb);
#pragma unroll
                for (int ni = 0; ni < 4; ni++) {
                    mma_f16(acc[mi][ni], a0, a1, a2, a3, bh[ni][0], bh[ni][1]);
                    mma_f16(acc[mi][ni], a0, a1, a2, a3, bl[ni][0], bl[ni][1]);
                }
            }
        }
        __syncthreads();
    }

    // epilogue: write f16 hi/lo pairs (exact split of fp32 accumulators)
    f16* oH = OH + (size_t)blade * BC;
    f16* oL = OL + (size_t)blade * BC;
#pragma unroll
    for (int mi = 0; mi < 4; mi++) {
        const int m0 = row0 + wm * 64 + mi * 16 + (lane >> 2);
#pragma unroll
        for (int ni = 0; ni < 4; ni++) {
            const int n = col0 + wn * 32 + ni * 8 + (lane & 3) * 2;
#pragma unroll
            for (int half = 0; half < 2; half++) {
                const int m = m0 + half * 8;
                const float v0 = acc[mi][ni][half * 2 + 0];
                const float v1 = acc[mi][ni][half * 2 + 1];
                const f16 h0 = __float2half_rn(v0), h1 = __float2half_rn(v1);
                const f16 l0 = __float2half_rn(v0 - __half2float(h0));
                const f16 l1 = __float2half_rn(v1 - __half2float(h1));
                *(__half2*)(oH + (size_t)m * Csz + n) = __halves2half2(h0, h1);
                *(__half2*)(oL + (size_t)m * Csz + n) = __halves2half2(l0, l1);
            }
        }
    }
}

// ---------------- conversions & elementwise passes ----------------
__global__ void conv_x(const float* __restrict__ X, f16* __restrict__ H) {
    const size_t idx = (size_t)blockIdx.x * 256 + threadIdx.x;
    const float4 a = *(const float4*)(X + idx * 8);
    const float4 b = *(const float4*)(X + idx * 8 + 4);
    const float v[8] = {a.x, a.y, a.z, a.w, b.x, b.y, b.z, b.w};
#pragma unroll
    for (int k = 0; k < 8; k++) H[k * BC + idx] = __float2half_rn(v[k]);
}

__global__ void conv_w(const float* __restrict__ W, f16* __restrict__ WH, f16* __restrict__ WL) {
    const int idx = blockIdx.x * 256 + threadIdx.x;  // o*256+i
    const float4 v = *(const float4*)(W + (size_t)idx * 4);
    const float g[4] = {v.x, v.y, v.z, v.w};
#pragma unroll
    for (int gg = 0; gg < 4; gg++) {
        const f16 h = __float2half_rn(g[gg]);
        WH[gg * 65536 + idx] = h;
        WL[gg * 65536 + idx] = __float2half_rn(g[gg] - __half2float(h));
    }
}

// silu on 2 consecutive elements per thread (half2 I/O)
__global__ void silu_pass(const f16* __restrict__ RH, const f16* __restrict__ RL,
                          const float* __restrict__ blin,
                          const float* __restrict__ pa, const float* __restrict__ pb,
                          f16* __restrict__ HH, f16* __restrict__ HL) {
    const size_t base = ((size_t)blockIdx.x * 256 + threadIdx.x) * 2;
    const int c0 = (int)(base & 255), c1 = c0 + 1;
    float y0[8], y1[8];
#pragma unroll
    for (int k = 0; k < 8; k++) {
        const __half2 vh = *(const __half2*)(RH + k * BC + base);
        const __half2 vl = *(const __half2*)(RL + k * BC + base);
        y0[k] = __half2float(__low2half(vh))  + __half2float(__low2half(vl));
        y1[k] = __half2float(__high2half(vh)) + __half2float(__high2half(vl));
    }
    y0[0] += blin[c0];  y1[0] += blin[c1];

    float g0[4], g1[4];
    {
        const float i00 = y0[0];
        const float i01 = y0[1]*y0[1] + y0[2]*y0[2] + y0[3]*y0[3];
        const float i02 = y0[4]*y0[4] + y0[5]*y0[5] + y0[6]*y0[6];
        const float i03 = y0[7]*y0[7];
        g0[0] = sigm(pa[c0*4+0]*i00 + pb[c0*4+0]);
        g0[1] = sigm(pa[c0*4+1]*i01 + pb[c0*4+1]);
        g0[2] = sigm(pa[c0*4+2]*i02 + pb[c0*4+2]);
        g0[3] = sigm(pa[c0*4+3]*i03 + pb[c0*4+3]);
        const float i10 = y1[0];
        const float i11 = y1[1]*y1[1] + y1[2]*y1[2] + y1[3]*y1[3];
        const float i12 = y1[4]*y1[4] + y1[5]*y1[5] + y1[6]*y1[6];
        const float i13 = y1[7]*y1[7];
        g1[0] = sigm(pa[c1*4+0]*i10 + pb[c1*4+0]);
        g1[1] = sigm(pa[c1*4+1]*i11 + pb[c1*4+1]);
        g1[2] = sigm(pa[c1*4+2]*i12 + pb[c1*4+2]);
        g1[3] = sigm(pa[c1*4+3]*i13 + pb[c1*4+3]);
    }
#pragma unroll
    for (int k = 0; k < 8; k++) {
        const float v0 = y0[k] * g0[GRc[k]];
        const float v1 = y1[k] * g1[GRc[k]];
        const f16 h0 = __float2half_rn(v0), h1 = __float2half_rn(v1);
        *(__half2*)(HH + k * BC + base) = __halves2half2(h0, h1);
        *(__half2*)(HL + k * BC + base) =
            __halves2half2(__float2half_rn(v0 - __half2float(h0)),
                           __float2half_rn(v1 - __half2float(h1)));
    }
}

// ---------------- fused grade-norm + geometric product + layernorm ----------------
template <int OUTMODE>
__global__ void __launch_bounds__(256, 4)
gp_ln(const f16* __restrict__ XhH, const f16* __restrict__ XhL,
      const f16* __restrict__ XrH, const f16* __restrict__ XrL,
      const f16* __restrict__ LfH, const f16* __restrict__ LfL,
      const float* __restrict__ NA, const float* __restrict__ GPW,
      const float* __restrict__ LNA, const float* __restrict__ BL,
      float* __restrict__ OutF, f16* __restrict__ OutH)
{
    const int b = blockIdx.x, c = threadIdx.x;
    const size_t idx = (size_t)b * Csz + c;

    float xv[8], rv[8], lv[8];
#pragma unroll
    for (int k = 0; k < 8; k++) {
        xv[k] = __half2float(XhH[k * BC + idx]) + __half2float(XhL[k * BC + idx]);
        rv[k] = __half2float(XrH[k * BC + idx]) + __half2float(XrL[k * BC + idx]);
        lv[k] = __half2float(LfH[k * BC + idx]) + __half2float(LfL[k * BC + idx]);
    }
    lv[0] += BL[c];

    // grade_norm on rv (fused; was a separate pass)
    {
        const float n0 = fabsf(rv[0]);
        const float n1 = sqrtf(rv[1]*rv[1] + rv[2]*rv[2] + rv[3]*rv[3]);
        const float n2 = sqrtf(rv[4]*rv[4] + rv[5]*rv[5] + rv[6]*rv[6]);
        const float n3 = fabsf(rv[7]);
        const float r0 = 1.0f / (fmaf(sigm(NA[c*4+0]), n0 - 1.0f, 1.0f) + 1e-6f);
        const float r1 = 1.0f / (fmaf(sigm(NA[c*4+1]), n1 - 1.0f, 1.0f) + 1e-6f);
        const float r2 = 1.0f / (fmaf(sigm(NA[c*4+2]), n2 - 1.0f, 1.0f) + 1e-6f);
        const float r3 = 1.0f / (fmaf(sigm(NA[c*4+3]), n3 - 1.0f, 1.0f) + 1e-6f);
        rv[0]*=r0; rv[1]*=r1; rv[2]*=r1; rv[3]*=r1;
        rv[4]*=r2; rv[5]*=r2; rv[6]*=r2; rv[7]*=r3;
    }

    float w20[20];
    {
        const float* wp = GPW + c * 20;
#pragma unroll
        for (int q = 0; q < 5; q++) *(float4*)&w20[q*4] = *(const float4*)(wp + q*4);
    }

    float gp[8] = {0,0,0,0,0,0,0,0};
#pragma unroll
    for (int i = 0; i < 8; i++) {
#pragma unroll
        for (int j = 0; j < 8; j++) {
            const int ma = ORD[i], mb = ORD[j];
            const int ko = IDXM[ma ^ mb];
            const int p  = PATHT[GRc[i]][GRc[j]][GRc[ko]];
            const bool neg = (NEGM[ma] >> mb) & 1;
            const float wv = neg ? -w20[p] : w20[p];
            gp[ko] = fmaf(wv, xv[i] * rv[j], gp[ko]);
        }
    }

    float s[8], sq = 0.0f;
#pragma unroll
    for (int k = 0; k < 8; k++) {
        s[k] = (lv[k] + gp[k]) * 0.70710678118654752f;
        sq = fmaf(s[k], s[k], sq);
    }
    float v = sqrtf(sq);

    __shared__ float red[8];
#pragma unroll
    for (int off = 16; off; off >>= 1) v += __shfl_xor_sync(0xffffffffu, v, off);
    if ((c & 31) == 0) red[c >> 5] = v;
    __syncthreads();
    const float tot = red[0]+red[1]+red[2]+red[3]+red[4]+red[5]+red[6]+red[7];
    const float scale = LNA[c] / (tot * (1.0f / 256.0f) + 1e-6f);

    if constexpr (OUTMODE == 0) {
#pragma unroll
        for (int k = 0; k < 8; k++)
            OutH[k * BC + idx] = __float2half_rn(s[k] * scale);
    } else {
        float4* dst = (float4*)(OutF + idx * 8);
        dst[0] = make_float4(s[0]*scale, s[1]*scale, s[2]*scale, s[3]*scale);
        dst[1] = make_float4(s[4]*scale, s[5]*scale, s[6]*scale, s[7]*scale);
    }
}

// ---------------- launch ----------------
extern "C" void kernel_launch(void* const* d_in, const int* in_sizes, int n_in,
                              void* d_out, int out_size)
{
    (void)in_sizes; (void)n_in; (void)out_size;
    const float* x = (const float*)d_in[0];
    float* out = (float*)d_out;

    cudaFuncSetAttribute(gemm_mma, cudaFuncAttributeMaxDynamicSharedMemorySize, GEMM_SMEM);

    f16 *rawH, *rawL, *xrH, *xrL, *lfH, *lfL, *hH, *hL, *inH, *wH, *wL;
    cudaGetSymbolAddress((void**)&rawH, g_rawH);
    cudaGetSymbolAddress((void**)&rawL, g_rawL);
    cudaGetSymbolAddress((void**)&xrH,  g_xrH);
    cudaGetSymbolAddress((void**)&xrL,  g_xrL);
    cudaGetSymbolAddress((void**)&lfH,  g_lfH);
    cudaGetSymbolAddress((void**)&lfL,  g_lfL);
    cudaGetSymbolAddress((void**)&hH,   g_hH);
    cudaGetSymbolAddress((void**)&hL,   g_hL);
    cudaGetSymbolAddress((void**)&inH,  g_inH);
    cudaGetSymbolAddress((void**)&wH,   g_wH);
    cudaGetSymbolAddress((void**)&wL,   g_wL);

    const int EB  = (int)(BC / 256);
    const int EB2 = (int)(BC / 512);
    const dim3 GG(Bsz / 128, Csz / 128, NBl);   // 64 x 2 x 8

    conv_x<<<EB, 256>>>(x, inH);

    for (int l = 0; l < 2; l++) {
        const float* const* P = (const float* const*)(d_in + 1 + 10 * l);
        // P: [w_lin, b_lin, silu_a, silu_b, w_right, w_left, b_left, norm_a, gp_w, ln_a]
        // Layer input always lives in inH: conv_x wrote it for l=0,
        // gp_ln<0> wrote it for l=1.
        conv_w<<<256, 256>>>(P[0], wH, wL);
        gemm_mma<<<GG, 256, GEMM_SMEM>>>(inH, wH, wL, rawH, rawL);
        silu_pass<<<EB2, 256>>>(rawH, rawL, P[1], P[2], P[3], hH, hL);

        conv_w<<<256, 256>>>(P[4], wH, wL);
        gemm_mma<<<GG, 256, GEMM_SMEM>>>(hH, wH, wL, xrH, xrL);

        conv_w<<<256, 256>>>(P[5], wH, wL);
        gemm_mma<<<GG, 256, GEMM_SMEM>>>(hH, wH, wL, lfH, lfL);

        if (l == 0)
            gp_ln<0><<<Bsz, 256>>>(hH, hL, xrH, xrL, lfH, lfL,
                                   P[7], P[8], P[9], P[6], nullptr, inH);
        else
            gp_ln<1><<<Bsz, 256>>>(hH, hL, xrH, xrL, lfH, lfL,
                                   P[7], P[8], P[9], P[6], out, nullptr);
    }
}

// round 14
// speedup vs baseline: 1.1675x; 1.1675x over previous
#include <cuda_runtime.h>
#include <cuda_fp16.h>
#include <cstdint>
#include <cstddef>

#define DEVI __device__ __forceinline__
typedef __half f16;

constexpr int Bsz = 8192, Csz = 256, NBl = 8;
constexpr size_t BC = (size_t)Bsz * Csz;   // elems per blade plane

// ---------------- scratch (device globals) ----------------
__device__ float g_raw[NBl * BC];   // w_lin gemm output (fp32)
__device__ float g_xr [NBl * BC];   // w_right gemm output (fp32, pre-gradenorm)
__device__ float g_lf [NBl * BC];   // w_left gemm output (fp32)
__device__ f16   g_inH[NBl * BC];   // layer input (fp16)
__device__ f16   g_hH [NBl * BC];   // h hi/lo (fp16 pair, for exact gp_ln reconstruction)
__device__ f16   g_hL [NBl * BC];
__device__ f16   g_wH [4 * Csz * Csz];
__device__ f16   g_wL [4 * Csz * Csz];

// ---------------- algebra tables ----------------
__device__ constexpr int ORD [8] = {0, 1, 2, 4, 3, 5, 6, 7};
__device__ constexpr int IDXM[8] = {0, 1, 2, 4, 3, 5, 6, 7};
__device__ constexpr int GRc [8] = {0, 1, 1, 1, 2, 2, 2, 3};
__device__ constexpr unsigned NEGM[8] = {0x00u, 0x00u, 0xAAu, 0xAAu,
                                         0x66u, 0x66u, 0xCCu, 0xCCu};
__device__ constexpr signed char PATHT[4][4][4] = {
  { { 0,-1,-1,-1}, {-1, 1,-1,-1}, {-1,-1, 2,-1}, {-1,-1,-1, 3} },
  { {-1, 4,-1,-1}, { 5,-1, 6,-1}, {-1, 7,-1, 8}, {-1,-1, 9,-1} },
  { {-1,-1,10,-1}, {-1,11,-1,12}, {13,-1,14,-1}, {-1,15,-1,-1} },
  { {-1,-1,-1,16}, {-1,-1,17,-1}, {-1,18,-1,-1}, {19,-1,-1,-1} }
};

DEVI float sigm(float x) { return 1.0f / (1.0f + __expf(-x)); }

DEVI uint32_t smem_u32(const void* p) {
    uint32_t a;
    asm("{ .reg .u64 t; cvta.to.shared.u64 t, %1; cvt.u32.u64 %0, t; }" : "=r"(a) : "l"(p));
    return a;
}

// ---- warp MMA primitives ----
DEVI void ldsm_x4(uint32_t& r0, uint32_t& r1, uint32_t& r2, uint32_t& r3, uint32_t addr) {
    asm volatile("ldmatrix.sync.aligned.m8n8.x4.shared.b16 {%0,%1,%2,%3}, [%4];"
                 : "=r"(r0), "=r"(r1), "=r"(r2), "=r"(r3) : "r"(addr));
}
DEVI void mma_f16(float* c, uint32_t a0, uint32_t a1, uint32_t a2, uint32_t a3,
                  uint32_t b0, uint32_t b1) {
    asm volatile(
        "mma.sync.aligned.m16n8k16.row.col.f32.f16.f16.f32 "
        "{%0,%1,%2,%3}, {%4,%5,%6,%7}, {%8,%9}, {%0,%1,%2,%3};"
        : "+f"(c[0]), "+f"(c[1]), "+f"(c[2]), "+f"(c[3])
        : "r"(a0), "r"(a1), "r"(a2), "r"(a3), "r"(b0), "r"(b1));
}
DEVI void cpa16(uint32_t dst, const void* src) {
    asm volatile("cp.async.cg.shared.global [%0], [%1], 16;" :: "r"(dst), "l"(src));
}
#define CPA_COMMIT()  asm volatile("cp.async.commit_group;" ::: "memory")
#define CPA_WAIT(n)   asm volatile("cp.async.wait_group %0;" :: "n"(n) : "memory")

// ---------------- mma.sync blade-plane GEMM (fp16 2-term, cp.async 2-stage) ----------------
constexpr int SKW = 40;
constexpr int ARR = 128 * SKW;
constexpr int STG = 3 * ARR;               // A, WH, WL per stage
constexpr int GEMM_SMEM = 2 * STG * (int)sizeof(f16);   // 61440 B

__global__ void __launch_bounds__(256, 2)
gemm_mma(const f16* __restrict__ A, const f16* __restrict__ WH,
         const f16* __restrict__ WL, float* __restrict__ OUT)
{
    extern __shared__ f16 smem[];
    const uint32_t sb = smem_u32(smem);

    const int tid = threadIdx.x, wid = tid >> 5, lane = tid & 31;
    const int blade = blockIdx.z, grade = GRc[blade];
    const int row0 = blockIdx.x * 128, col0 = blockIdx.y * 128;
    const int wm = wid & 1, wn = wid >> 1;

    const f16* aP  = A  + (size_t)blade * BC + (size_t)row0 * Csz;
    const f16* wHp = WH + (size_t)grade * Csz * Csz + (size_t)col0 * Csz;
    const f16* wLp = WL + (size_t)grade * Csz * Csz + (size_t)col0 * Csz;

    float acc[4][4][4];
#pragma unroll
    for (int mi = 0; mi < 4; mi++)
#pragma unroll
        for (int ni = 0; ni < 4; ni++)
#pragma unroll
            for (int q = 0; q < 4; q++) acc[mi][ni][q] = 0.0f;

    const int lq = lane >> 3, lr = lane & 7;
    const uint32_t offA = (uint32_t)(((lq & 1) * 8 + lr) * SKW + (lq >> 1) * 8) * 2;
    const uint32_t offB = (uint32_t)(((lq >> 1) * 8 + lr) * SKW + (lq & 1) * 8) * 2;

    auto load_chunk = [&](int ch, int s) {
        const uint32_t base = sb + (uint32_t)(s * STG) * 2;
#pragma unroll
        for (int it = 0; it < 2; it++) {
            const int t = tid + it * 256;
            const int r = t >> 2, c = t & 3;
            const size_t src = (size_t)r * Csz + ch * 32 + c * 8;
            const uint32_t d = (uint32_t)(r * SKW + c * 8) * 2;
            cpa16(base + 0 * ARR * 2 + d, aP  + src);
            cpa16(base + 1 * ARR * 2 + d, wHp + src);
            cpa16(base + 2 * ARR * 2 + d, wLp + src);
        }
        CPA_COMMIT();
    };

    load_chunk(0, 0);

    for (int ch = 0; ch < 8; ch++) {
        const int s = ch & 1;
        if (ch + 1 < 8) { load_chunk(ch + 1, (ch + 1) & 1); CPA_WAIT(1); }
        else            { CPA_WAIT(0); }
        __syncthreads();

        const uint32_t bA  = sb + (uint32_t)(s * STG + 0 * ARR) * 2;
        const uint32_t bBH = sb + (uint32_t)(s * STG + 1 * ARR) * 2;
        const uint32_t bBL = sb + (uint32_t)(s * STG + 2 * ARR) * 2;

#pragma unroll
        for (int kh = 0; kh < 2; kh++) {
            const uint32_t kb = (uint32_t)(kh * 16) * 2;
            uint32_t bh[4][2], bl[4][2];
#pragma unroll
            for (int nb = 0; nb < 2; nb++) {
                const uint32_t nbase = (uint32_t)((wn * 32 + nb * 16) * SKW) * 2;
                ldsm_x4(bh[nb*2][0], bh[nb*2][1], bh[nb*2+1][0], bh[nb*2+1][1],
                        bBH + nbase + offB + kb);
                ldsm_x4(bl[nb*2][0], bl[nb*2][1], bl[nb*2+1][0], bl[nb*2+1][1],
                        bBL + nbase + offB + kb);
            }
#pragma unroll
            for (int mi = 0; mi < 4; mi++) {
                const uint32_t mbase = (uint32_t)((wm * 64 + mi * 16) * SKW) * 2;
                uint32_t a0, a1, a2, a3;
                ldsm_x4(a0, a1, a2, a3, bA + mbase + offA + kb);
#pragma unroll
                for (int ni = 0; ni < 4; ni++) {
                    mma_f16(acc[mi][ni], a0, a1, a2, a3, bh[ni][0], bh[ni][1]);
                    mma_f16(acc[mi][ni], a0, a1, a2, a3, bl[ni][0], bl[ni][1]);
                }
            }
        }
        __syncthreads();
    }

    // epilogue: write fp32 planar (R11 layout — proven fastest)
    float* outp = OUT + (size_t)blade * BC;
#pragma unroll
    for (int mi = 0; mi < 4; mi++) {
        const int m0 = row0 + wm * 64 + mi * 16 + (lane >> 2);
#pragma unroll
        for (int ni = 0; ni < 4; ni++) {
            const int n = col0 + wn * 32 + ni * 8 + (lane & 3) * 2;
            *(float2*)(outp + (size_t)m0 * Csz + n)       = make_float2(acc[mi][ni][0], acc[mi][ni][1]);
            *(float2*)(outp + (size_t)(m0 + 8) * Csz + n) = make_float2(acc[mi][ni][2], acc[mi][ni][3]);
        }
    }
}

// ---------------- conversions & elementwise passes ----------------
__global__ void conv_x(const float* __restrict__ X, f16* __restrict__ H) {
    const size_t idx = (size_t)blockIdx.x * 256 + threadIdx.x;
    const float4 a = *(const float4*)(X + idx * 8);
    const float4 b = *(const float4*)(X + idx * 8 + 4);
    const float v[8] = {a.x, a.y, a.z, a.w, b.x, b.y, b.z, b.w};
#pragma unroll
    for (int k = 0; k < 8; k++) H[k * BC + idx] = __float2half_rn(v[k]);
}

__global__ void conv_w(const float* __restrict__ W, f16* __restrict__ WH, f16* __restrict__ WL) {
    const int idx = blockIdx.x * 256 + threadIdx.x;  // o*256+i
    const float4 v = *(const float4*)(W + (size_t)idx * 4);
    const float g[4] = {v.x, v.y, v.z, v.w};
#pragma unroll
    for (int gg = 0; gg < 4; gg++) {
        const f16 h = __float2half_rn(g[gg]);
        WH[gg * 65536 + idx] = h;
        WL[gg * 65536 + idx] = __float2half_rn(g[gg] - __half2float(h));
    }
}

// silu: 1 elem/thread, fp32 raw in, f16 hi/lo out (R11 version — measured 24us)
__global__ void silu_pass(const float* __restrict__ RAW, const float* __restrict__ blin,
                          const float* __restrict__ pa, const float* __restrict__ pb,
                          f16* __restrict__ HH, f16* __restrict__ HL) {
    const size_t idx = (size_t)blockIdx.x * 256 + threadIdx.x;
    const int c = (int)(idx & 255);
    float y[8];
#pragma unroll
    for (int k = 0; k < 8; k++) y[k] = RAW[k * BC + idx];
    y[0] += blin[c];
    const float i0 = y[0];
    const float i1 = y[1]*y[1] + y[2]*y[2] + y[3]*y[3];
    const float i2 = y[4]*y[4] + y[5]*y[5] + y[6]*y[6];
    const float i3 = y[7]*y[7];
    const float g0 = sigm(pa[c*4+0] * i0 + pb[c*4+0]);
    const float g1 = sigm(pa[c*4+1] * i1 + pb[c*4+1]);
    const float g2 = sigm(pa[c*4+2] * i2 + pb[c*4+2]);
    const float g3 = sigm(pa[c*4+3] * i3 + pb[c*4+3]);
    const float gk[8] = {g0, g1, g1, g1, g2, g2, g2, g3};
#pragma unroll
    for (int k = 0; k < 8; k++) {
        const float v = y[k] * gk[k];
        const f16 h = __float2half_rn(v);
        HH[k * BC + idx] = h;
        HL[k * BC + idx] = __float2half_rn(v - __half2float(h));
    }
}

// ---------------- fused grade-norm + geometric product + layernorm ----------------
// rv computed from RAW w_right output with grade-norm applied inline.
template <int OUTMODE>
__global__ void __launch_bounds__(256, 4)
gp_ln(const f16* __restrict__ XhH, const f16* __restrict__ XhL,
      const float* __restrict__ XRraw, const float* __restrict__ Lf,
      const float* __restrict__ NA, const float* __restrict__ GPW,
      const float* __restrict__ LNA, const float* __restrict__ BL,
      float* __restrict__ OutF, f16* __restrict__ OutH)
{
    const int b = blockIdx.x, c = threadIdx.x;
    const size_t idx = (size_t)b * Csz + c;

    float xv[8], rv[8], lv[8];
#pragma unroll
    for (int k = 0; k < 8; k++) {
        xv[k] = __half2float(XhH[k * BC + idx]) + __half2float(XhL[k * BC + idx]);
        rv[k] = XRraw[k * BC + idx];
        lv[k] = Lf[k * BC + idx];
    }
    lv[0] += BL[c];

    // grade_norm on rv (fused; replaces the old gnorm_pass kernel)
    {
        const float n0 = fabsf(rv[0]);
        const float n1 = sqrtf(rv[1]*rv[1] + rv[2]*rv[2] + rv[3]*rv[3]);
        const float n2 = sqrtf(rv[4]*rv[4] + rv[5]*rv[5] + rv[6]*rv[6]);
        const float n3 = fabsf(rv[7]);
        const float r0 = 1.0f / (fmaf(sigm(NA[c*4+0]), n0 - 1.0f, 1.0f) + 1e-6f);
        const float r1 = 1.0f / (fmaf(sigm(NA[c*4+1]), n1 - 1.0f, 1.0f) + 1e-6f);
        const float r2 = 1.0f / (fmaf(sigm(NA[c*4+2]), n2 - 1.0f, 1.0f) + 1e-6f);
        const float r3 = 1.0f / (fmaf(sigm(NA[c*4+3]), n3 - 1.0f, 1.0f) + 1e-6f);
        rv[0]*=r0; rv[1]*=r1; rv[2]*=r1; rv[3]*=r1;
        rv[4]*=r2; rv[5]*=r2; rv[6]*=r2; rv[7]*=r3;
    }

    float w20[20];
    {
        const float* wp = GPW + c * 20;
#pragma unroll
        for (int q = 0; q < 5; q++) *(float4*)&w20[q*4] = *(const float4*)(wp + q*4);
    }

    float gp[8] = {0,0,0,0,0,0,0,0};
#pragma unroll
    for (int i = 0; i < 8; i++) {
#pragma unroll
        for (int j = 0; j < 8; j++) {
            const int ma = ORD[i], mb = ORD[j];
            const int ko = IDXM[ma ^ mb];
            const int p  = PATHT[GRc[i]][GRc[j]][GRc[ko]];
            const bool neg = (NEGM[ma] >> mb) & 1;
            const float wv = neg ? -w20[p] : w20[p];
            gp[ko] = fmaf(wv, xv[i] * rv[j], gp[ko]);
        }
    }

    float s[8], sq = 0.0f;
#pragma unroll
    for (int k = 0; k < 8; k++) {
        s[k] = (lv[k] + gp[k]) * 0.70710678118654752f;
        sq = fmaf(s[k], s[k], sq);
    }
    float v = sqrtf(sq);

    __shared__ float red[8];
#pragma unroll
    for (int off = 16; off; off >>= 1) v += __shfl_xor_sync(0xffffffffu, v, off);
    if ((c & 31) == 0) red[c >> 5] = v;
    __syncthreads();
    const float tot = red[0]+red[1]+red[2]+red[3]+red[4]+red[5]+red[6]+red[7];
    const float scale = LNA[c] / (tot * (1.0f / 256.0f) + 1e-6f);

    if constexpr (OUTMODE == 0) {
#pragma unroll
        for (int k = 0; k < 8; k++)
            OutH[k * BC + idx] = __float2half_rn(s[k] * scale);
    } else {
        float4* dst = (float4*)(OutF + idx * 8);
        dst[0] = make_float4(s[0]*scale, s[1]*scale, s[2]*scale, s[3]*scale);
        dst[1] = make_float4(s[4]*scale, s[5]*scale, s[6]*scale, s[7]*scale);
    }
}

// ---------------- launch ----------------
extern "C" void kernel_launch(void* const* d_in, const int* in_sizes, int n_in,
                              void* d_out, int out_size)
{
    (void)in_sizes; (void)n_in; (void)out_size;
    const float* x = (const float*)d_in[0];
    float* out = (float*)d_out;

    cudaFuncSetAttribute(gemm_mma, cudaFuncAttributeMaxDynamicSharedMemorySize, GEMM_SMEM);

    float *raw, *xr, *lf;
    f16 *inH, *hH, *hL, *wH, *wL;
    cudaGetSymbolAddress((void**)&raw, g_raw);
    cudaGetSymbolAddress((void**)&xr,  g_xr);
    cudaGetSymbolAddress((void**)&lf,  g_lf);
    cudaGetSymbolAddress((void**)&inH, g_inH);
    cudaGetSymbolAddress((void**)&hH,  g_hH);
    cudaGetSymbolAddress((void**)&hL,  g_hL);
    cudaGetSymbolAddress((void**)&wH,  g_wH);
    cudaGetSymbolAddress((void**)&wL,  g_wL);

    const int EB = (int)(BC / 256);
    const dim3 GG(Bsz / 128, Csz / 128, NBl);   // 64 x 2 x 8

    conv_x<<<EB, 256>>>(x, inH);

    for (int l = 0; l < 2; l++) {
        const float* const* P = (const float* const*)(d_in + 1 + 10 * l);
        // P: [w_lin, b_lin, silu_a, silu_b, w_right, w_left, b_left, norm_a, gp_w, ln_a]
        // Layer input always lives in inH (conv_x for l=0, gp_ln<0> for l=1).
        conv_w<<<256, 256>>>(P[0], wH, wL);
        gemm_mma<<<GG, 256, GEMM_SMEM>>>(inH, wH, wL, raw);
        silu_pass<<<EB, 256>>>(raw, P[1], P[2], P[3], hH, hL);

        conv_w<<<256, 256>>>(P[4], wH, wL);
        gemm_mma<<<GG, 256, GEMM_SMEM>>>(hH, wH, wL, xr);   // raw w_right output

        conv_w<<<256, 256>>>(P[5], wH, wL);
        gemm_mma<<<GG, 256, GEMM_SMEM>>>(hH, wH, wL, lf);

        if (l == 0)
            gp_ln<0><<<Bsz, 256>>>(hH, hL, xr, lf, P[7], P[8], P[9], P[6],
                                   nullptr, inH);
        else
            gp_ln<1><<<Bsz, 256>>>(hH, hL, xr, lf, P[7], P[8], P[9], P[6],
                                   out, nullptr);
    }
}

// round 15
// speedup vs baseline: 1.5379x; 1.3172x over previous
#include <cuda_runtime.h>
#include <cuda_fp16.h>
#include <cstdint>
#include <cstddef>

#define DEVI __device__ __forceinline__
typedef __half f16;

constexpr int Bsz = 8192, Csz = 256, NBl = 8;
constexpr size_t BC = (size_t)Bsz * Csz;   // elems per blade plane

// ---------------- scratch (device globals) ----------------
__device__ float g_raw[NBl * BC];   // w_lin gemm output (fp32)
__device__ float g_xr [NBl * BC];   // w_right gemm output (fp32, pre-gradenorm)
__device__ float g_lf [NBl * BC];   // w_left gemm output (fp32)
__device__ f16   g_inH[NBl * BC];   // layer input (fp16)
__device__ f16   g_hH [NBl * BC];   // h hi/lo (fp16 pair, for exact gp_ln reconstruction)
__device__ f16   g_hL [NBl * BC];
__device__ f16   g_wH [4 * Csz * Csz];

// ---------------- algebra tables ----------------
__device__ constexpr int ORD [8] = {0, 1, 2, 4, 3, 5, 6, 7};
__device__ constexpr int IDXM[8] = {0, 1, 2, 4, 3, 5, 6, 7};
__device__ constexpr int GRc [8] = {0, 1, 1, 1, 2, 2, 2, 3};
__device__ constexpr unsigned NEGM[8] = {0x00u, 0x00u, 0xAAu, 0xAAu,
                                         0x66u, 0x66u, 0xCCu, 0xCCu};
__device__ constexpr signed char PATHT[4][4][4] = {
  { { 0,-1,-1,-1}, {-1, 1,-1,-1}, {-1,-1, 2,-1}, {-1,-1,-1, 3} },
  { {-1, 4,-1,-1}, { 5,-1, 6,-1}, {-1, 7,-1, 8}, {-1,-1, 9,-1} },
  { {-1,-1,10,-1}, {-1,11,-1,12}, {13,-1,14,-1}, {-1,15,-1,-1} },
  { {-1,-1,-1,16}, {-1,-1,17,-1}, {-1,18,-1,-1}, {19,-1,-1,-1} }
};

DEVI float sigm(float x) { return 1.0f / (1.0f + __expf(-x)); }

DEVI uint32_t smem_u32(const void* p) {
    uint32_t a;
    asm("{ .reg .u64 t; cvta.to.shared.u64 t, %1; cvt.u32.u64 %0, t; }" : "=r"(a) : "l"(p));
    return a;
}

// ---- warp MMA primitives ----
DEVI void ldsm_x4(uint32_t& r0, uint32_t& r1, uint32_t& r2, uint32_t& r3, uint32_t addr) {
    asm volatile("ldmatrix.sync.aligned.m8n8.x4.shared.b16 {%0,%1,%2,%3}, [%4];"
                 : "=r"(r0), "=r"(r1), "=r"(r2), "=r"(r3) : "r"(addr));
}
DEVI void mma_f16(float* c, uint32_t a0, uint32_t a1, uint32_t a2, uint32_t a3,
                  uint32_t b0, uint32_t b1) {
    asm volatile(
        "mma.sync.aligned.m16n8k16.row.col.f32.f16.f16.f32 "
        "{%0,%1,%2,%3}, {%4,%5,%6,%7}, {%8,%9}, {%0,%1,%2,%3};"
        : "+f"(c[0]), "+f"(c[1]), "+f"(c[2]), "+f"(c[3])
        : "r"(a0), "r"(a1), "r"(a2), "r"(a3), "r"(b0), "r"(b1));
}
DEVI void cpa16(uint32_t dst, const void* src) {
    asm volatile("cp.async.cg.shared.global [%0], [%1], 16;" :: "r"(dst), "l"(src));
}
#define CPA_COMMIT()  asm volatile("cp.async.commit_group;" ::: "memory")
#define CPA_WAIT(n)   asm volatile("cp.async.wait_group %0;" :: "n"(n) : "memory")

// ---------------- mma.sync blade-plane GEMM (pure fp16 single-term, cp.async 2-stage) ----------------
constexpr int SKW = 40;
constexpr int ARR = 128 * SKW;
constexpr int STG = 2 * ARR;               // A, WH per stage
constexpr int GEMM_SMEM = 2 * STG * (int)sizeof(f16);   // 40960 B

__global__ void __launch_bounds__(256, 2)
gemm_mma(const f16* __restrict__ A, const f16* __restrict__ WH,
         float* __restrict__ OUT)
{
    extern __shared__ f16 smem[];
    const uint32_t sb = smem_u32(smem);

    const int tid = threadIdx.x, wid = tid >> 5, lane = tid & 31;
    const int blade = blockIdx.z, grade = GRc[blade];
    const int row0 = blockIdx.x * 128, col0 = blockIdx.y * 128;
    const int wm = wid & 1, wn = wid >> 1;

    const f16* aP  = A  + (size_t)blade * BC + (size_t)row0 * Csz;
    const f16* wHp = WH + (size_t)grade * Csz * Csz + (size_t)col0 * Csz;

    float acc[4][4][4];
#pragma unroll
    for (int mi = 0; mi < 4; mi++)
#pragma unroll
        for (int ni = 0; ni < 4; ni++)
#pragma unroll
            for (int q = 0; q < 4; q++) acc[mi][ni][q] = 0.0f;

    const int lq = lane >> 3, lr = lane & 7;
    const uint32_t offA = (uint32_t)(((lq & 1) * 8 + lr) * SKW + (lq >> 1) * 8) * 2;
    const uint32_t offB = (uint32_t)(((lq >> 1) * 8 + lr) * SKW + (lq & 1) * 8) * 2;

    auto load_chunk = [&](int ch, int s) {
        const uint32_t base = sb + (uint32_t)(s * STG) * 2;
#pragma unroll
        for (int it = 0; it < 2; it++) {
            const int t = tid + it * 256;
            const int r = t >> 2, c = t & 3;
            const size_t src = (size_t)r * Csz + ch * 32 + c * 8;
            const uint32_t d = (uint32_t)(r * SKW + c * 8) * 2;
            cpa16(base + 0 * ARR * 2 + d, aP  + src);
            cpa16(base + 1 * ARR * 2 + d, wHp + src);
        }
        CPA_COMMIT();
    };

    load_chunk(0, 0);

    for (int ch = 0; ch < 8; ch++) {
        const int s = ch & 1;
        if (ch + 1 < 8) { load_chunk(ch + 1, (ch + 1) & 1); CPA_WAIT(1); }
        else            { CPA_WAIT(0); }
        __syncthreads();

        const uint32_t bA  = sb + (uint32_t)(s * STG + 0 * ARR) * 2;
        const uint32_t bBH = sb + (uint32_t)(s * STG + 1 * ARR) * 2;

#pragma unroll
        for (int kh = 0; kh < 2; kh++) {
            const uint32_t kb = (uint32_t)(kh * 16) * 2;
            uint32_t bh[4][2];
#pragma unroll
            for (int nb = 0; nb < 2; nb++) {
                const uint32_t nbase = (uint32_t)((wn * 32 + nb * 16) * SKW) * 2;
                ldsm_x4(bh[nb*2][0], bh[nb*2][1], bh[nb*2+1][0], bh[nb*2+1][1],
                        bBH + nbase + offB + kb);
            }
#pragma unroll
            for (int mi = 0; mi < 4; mi++) {
                const uint32_t mbase = (uint32_t)((wm * 64 + mi * 16) * SKW) * 2;
                uint32_t a0, a1, a2, a3;
                ldsm_x4(a0, a1, a2, a3, bA + mbase + offA + kb);
#pragma unroll
                for (int ni = 0; ni < 4; ni++)
                    mma_f16(acc[mi][ni], a0, a1, a2, a3, bh[ni][0], bh[ni][1]);
            }
        }
        __syncthreads();
    }

    // epilogue: write fp32 planar
    float* outp = OUT + (size_t)blade * BC;
#pragma unroll
    for (int mi = 0; mi < 4; mi++) {
        const int m0 = row0 + wm * 64 + mi * 16 + (lane >> 2);
#pragma unroll
        for (int ni = 0; ni < 4; ni++) {
            const int n = col0 + wn * 32 + ni * 8 + (lane & 3) * 2;
            *(float2*)(outp + (size_t)m0 * Csz + n)       = make_float2(acc[mi][ni][0], acc[mi][ni][1]);
            *(float2*)(outp + (size_t)(m0 + 8) * Csz + n) = make_float2(acc[mi][ni][2], acc[mi][ni][3]);
        }
    }
}

// ---------------- conversions & elementwise passes ----------------
__global__ void conv_x(const float* __restrict__ X, f16* __restrict__ H) {
    const size_t idx = (size_t)blockIdx.x * 256 + threadIdx.x;
    const float4 a = *(const float4*)(X + idx * 8);
    const float4 b = *(const float4*)(X + idx * 8 + 4);
    const float v[8] = {a.x, a.y, a.z, a.w, b.x, b.y, b.z, b.w};
#pragma unroll
    for (int k = 0; k < 8; k++) H[k * BC + idx] = __float2half_rn(v[k]);
}

__global__ void conv_w(const float* __restrict__ W, f16* __restrict__ WH) {
    const int idx = blockIdx.x * 256 + threadIdx.x;  // o*256+i
    const float4 v = *(const float4*)(W + (size_t)idx * 4);
    WH[0 * 65536 + idx] = __float2half_rn(v.x);
    WH[1 * 65536 + idx] = __float2half_rn(v.y);
    WH[2 * 65536 + idx] = __float2half_rn(v.z);
    WH[3 * 65536 + idx] = __float2half_rn(v.w);
}

// silu: 1 elem/thread, fp32 raw in, f16 hi/lo out
__global__ void silu_pass(const float* __restrict__ RAW, const float* __restrict__ blin,
                          const float* __restrict__ pa, const float* __restrict__ pb,
                          f16* __restrict__ HH, f16* __restrict__ HL) {
    const size_t idx = (size_t)blockIdx.x * 256 + threadIdx.x;
    const int c = (int)(idx & 255);
    float y[8];
#pragma unroll
    for (int k = 0; k < 8; k++) y[k] = RAW[k * BC + idx];
    y[0] += blin[c];
    const float i0 = y[0];
    const float i1 = y[1]*y[1] + y[2]*y[2] + y[3]*y[3];
    const float i2 = y[4]*y[4] + y[5]*y[5] + y[6]*y[6];
    const float i3 = y[7]*y[7];
    const float g0 = sigm(pa[c*4+0] * i0 + pb[c*4+0]);
    const float g1 = sigm(pa[c*4+1] * i1 + pb[c*4+1]);
    const float g2 = sigm(pa[c*4+2] * i2 + pb[c*4+2]);
    const float g3 = sigm(pa[c*4+3] * i3 + pb[c*4+3]);
    const float gk[8] = {g0, g1, g1, g1, g2, g2, g2, g3};
#pragma unroll
    for (int k = 0; k < 8; k++) {
        const float v = y[k] * gk[k];
        const f16 h = __float2half_rn(v);
        HH[k * BC + idx] = h;
        HL[k * BC + idx] = __float2half_rn(v - __half2float(h));
    }
}

// ---------------- fused grade-norm + geometric product + layernorm ----------------
template <int OUTMODE>
__global__ void __launch_bounds__(256, 4)
gp_ln(const f16* __restrict__ XhH, const f16* __restrict__ XhL,
      const float* __restrict__ XRraw, const float* __restrict__ Lf,
      const float* __restrict__ NA, const float* __restrict__ GPW,
      const float* __restrict__ LNA, const float* __restrict__ BL,
      float* __restrict__ OutF, f16* __restrict__ OutH)
{
    const int b = blockIdx.x, c = threadIdx.x;
    const size_t idx = (size_t)b * Csz + c;

    float xv[8], rv[8], lv[8];
#pragma unroll
    for (int k = 0; k < 8; k++) {
        xv[k] = __half2float(XhH[k * BC + idx]) + __half2float(XhL[k * BC + idx]);
        rv[k] = XRraw[k * BC + idx];
        lv[k] = Lf[k * BC + idx];
    }
    lv[0] += BL[c];

    // grade_norm on rv (fused)
    {
        const float n0 = fabsf(rv[0]);
        const float n1 = sqrtf(rv[1]*rv[1] + rv[2]*rv[2] + rv[3]*rv[3]);
        const float n2 = sqrtf(rv[4]*rv[4] + rv[5]*rv[5] + rv[6]*rv[6]);
        const float n3 = fabsf(rv[7]);
        const float r0 = 1.0f / (fmaf(sigm(NA[c*4+0]), n0 - 1.0f, 1.0f) + 1e-6f);
        const float r1 = 1.0f / (fmaf(sigm(NA[c*4+1]), n1 - 1.0f, 1.0f) + 1e-6f);
        const float r2 = 1.0f / (fmaf(sigm(NA[c*4+2]), n2 - 1.0f, 1.0f) + 1e-6f);
        const float r3 = 1.0f / (fmaf(sigm(NA[c*4+3]), n3 - 1.0f, 1.0f) + 1e-6f);
        rv[0]*=r0; rv[1]*=r1; rv[2]*=r1; rv[3]*=r1;
        rv[4]*=r2; rv[5]*=r2; rv[6]*=r2; rv[7]*=r3;
    }

    float w20[20];
    {
        const float* wp = GPW + c * 20;
#pragma unroll
        for (int q = 0; q < 5; q++) *(float4*)&w20[q*4] = *(const float4*)(wp + q*4);
    }

    float gp[8] = {0,0,0,0,0,0,0,0};
#pragma unroll
    for (int i = 0; i < 8; i++) {
#pragma unroll
        for (int j = 0; j < 8; j++) {
            const int ma = ORD[i], mb = ORD[j];
            const int ko = IDXM[ma ^ mb];
            const int p  = PATHT[GRc[i]][GRc[j]][GRc[ko]];
            const bool neg = (NEGM[ma] >> mb) & 1;
            const float wv = neg ? -w20[p] : w20[p];
            gp[ko] = fmaf(wv, xv[i] * rv[j], gp[ko]);
        }
    }

    float s[8], sq = 0.0f;
#pragma unroll
    for (int k = 0; k < 8; k++) {
        s[k] = (lv[k] + gp[k]) * 0.70710678118654752f;
        sq = fmaf(s[k], s[k], sq);
    }
    float v = sqrtf(sq);

    __shared__ float red[8];
#pragma unroll
    for (int off = 16; off; off >>= 1) v += __shfl_xor_sync(0xffffffffu, v, off);
    if ((c & 31) == 0) red[c >> 5] = v;
    __syncthreads();
    const float tot = red[0]+red[1]+red[2]+red[3]+red[4]+red[5]+red[6]+red[7];
    const float scale = LNA[c] / (tot * (1.0f / 256.0f) + 1e-6f);

    if constexpr (OUTMODE == 0) {
#pragma unroll
        for (int k = 0; k < 8; k++)
            OutH[k * BC + idx] = __float2half_rn(s[k] * scale);
    } else {
        float4* dst = (float4*)(OutF + idx * 8);
        dst[0] = make_float4(s[0]*scale, s[1]*scale, s[2]*scale, s[3]*scale);
        dst[1] = make_float4(s[4]*scale, s[5]*scale, s[6]*scale, s[7]*scale);
    }
}

// ---------------- launch ----------------
extern "C" void kernel_launch(void* const* d_in, const int* in_sizes, int n_in,
                              void* d_out, int out_size)
{
    (void)in_sizes; (void)n_in; (void)out_size;
    const float* x = (const float*)d_in[0];
    float* out = (float*)d_out;

    cudaFuncSetAttribute(gemm_mma, cudaFuncAttributeMaxDynamicSharedMemorySize, GEMM_SMEM);

    float *raw, *xr, *lf;
    f16 *inH, *hH, *hL, *wH;
    cudaGetSymbolAddress((void**)&raw, g_raw);
    cudaGetSymbolAddress((void**)&xr,  g_xr);
    cudaGetSymbolAddress((void**)&lf,  g_lf);
    cudaGetSymbolAddress((void**)&inH, g_inH);
    cudaGetSymbolAddress((void**)&hH,  g_hH);
    cudaGetSymbolAddress((void**)&hL,  g_hL);
    cudaGetSymbolAddress((void**)&wH,  g_wH);

    const int EB = (int)(BC / 256);
    const dim3 GG(Bsz / 128, Csz / 128, NBl);   // 64 x 2 x 8

    conv_x<<<EB, 256>>>(x, inH);

    for (int l = 0; l < 2; l++) {
        const float* const* P = (const float* const*)(d_in + 1 + 10 * l);
        // P: [w_lin, b_lin, silu_a, silu_b, w_right, w_left, b_left, norm_a, gp_w, ln_a]
        // Layer input always lives in inH (conv_x for l=0, gp_ln<0> for l=1).
        conv_w<<<256, 256>>>(P[0], wH);
        gemm_mma<<<GG, 256, GEMM_SMEM>>>(inH, wH, raw);
        silu_pass<<<EB, 256>>>(raw, P[1], P[2], P[3], hH, hL);

        conv_w<<<256, 256>>>(P[4], wH);
        gemm_mma<<<GG, 256, GEMM_SMEM>>>(hH, wH, xr);   // raw w_right output

        conv_w<<<256, 256>>>(P[5], wH);
        gemm_mma<<<GG, 256, GEMM_SMEM>>>(hH, wH, lf);

        if (l == 0)
            gp_ln<0><<<Bsz, 256>>>(hH, hL, xr, lf, P[7], P[8], P[9], P[6],
                                   nullptr, inH);
        else
            gp_ln<1><<<Bsz, 256>>>(hH, hL, xr, lf, P[7], P[8], P[9], P[6],
                                   out, nullptr);
    }
}

// round 16
// speedup vs baseline: 1.5994x; 1.0400x over previous
#include <cuda_runtime.h>
#include <cuda_fp16.h>
#include <cstdint>
#include <cstddef>

#define DEVI __device__ __forceinline__
typedef __half f16;

constexpr int Bsz = 8192, Csz = 256, NBl = 8;
constexpr size_t BC = (size_t)Bsz * Csz;   // elems per blade plane

// ---------------- scratch (device globals) ----------------
__device__ float g_raw[NBl * BC];   // w_lin gemm output (fp32)
__device__ f16   g_xr [NBl * BC];   // w_right gemm output (f16, pre-gradenorm)
__device__ f16   g_lf [NBl * BC];   // w_left gemm output (f16)
__device__ f16   g_inH[NBl * BC];   // layer input (fp16)
__device__ f16   g_hH [NBl * BC];   // h hi/lo (fp16 pair, for exact gp_ln reconstruction)
__device__ f16   g_hL [NBl * BC];
__device__ f16   g_wA [4 * Csz * Csz];   // w_lin (f16)
__device__ f16   g_wB [4 * Csz * Csz];   // w_right
__device__ f16   g_wC [4 * Csz * Csz];   // w_left

// ---------------- algebra tables ----------------
__device__ constexpr int ORD [8] = {0, 1, 2, 4, 3, 5, 6, 7};
__device__ constexpr int IDXM[8] = {0, 1, 2, 4, 3, 5, 6, 7};
__device__ constexpr int GRc [8] = {0, 1, 1, 1, 2, 2, 2, 3};
__device__ constexpr unsigned NEGM[8] = {0x00u, 0x00u, 0xAAu, 0xAAu,
                                         0x66u, 0x66u, 0xCCu, 0xCCu};
__device__ constexpr signed char PATHT[4][4][4] = {
  { { 0,-1,-1,-1}, {-1, 1,-1,-1}, {-1,-1, 2,-1}, {-1,-1,-1, 3} },
  { {-1, 4,-1,-1}, { 5,-1, 6,-1}, {-1, 7,-1, 8}, {-1,-1, 9,-1} },
  { {-1,-1,10,-1}, {-1,11,-1,12}, {13,-1,14,-1}, {-1,15,-1,-1} },
  { {-1,-1,-1,16}, {-1,-1,17,-1}, {-1,18,-1,-1}, {19,-1,-1,-1} }
};

DEVI float sigm(float x) { return 1.0f / (1.0f + __expf(-x)); }

DEVI uint32_t smem_u32(const void* p) {
    uint32_t a;
    asm("{ .reg .u64 t; cvta.to.shared.u64 t, %1; cvt.u32.u64 %0, t; }" : "=r"(a) : "l"(p));
    return a;
}

// ---- warp MMA primitives ----
DEVI void ldsm_x4(uint32_t& r0, uint32_t& r1, uint32_t& r2, uint32_t& r3, uint32_t addr) {
    asm volatile("ldmatrix.sync.aligned.m8n8.x4.shared.b16 {%0,%1,%2,%3}, [%4];"
                 : "=r"(r0), "=r"(r1), "=r"(r2), "=r"(r3) : "r"(addr));
}
DEVI void mma_f16(float* c, uint32_t a0, uint32_t a1, uint32_t a2, uint32_t a3,
                  uint32_t b0, uint32_t b1) {
    asm volatile(
        "mma.sync.aligned.m16n8k16.row.col.f32.f16.f16.f32 "
        "{%0,%1,%2,%3}, {%4,%5,%6,%7}, {%8,%9}, {%0,%1,%2,%3};"
        : "+f"(c[0]), "+f"(c[1]), "+f"(c[2]), "+f"(c[3])
        : "r"(a0), "r"(a1), "r"(a2), "r"(a3), "r"(b0), "r"(b1));
}
DEVI void cpa16(uint32_t dst, const void* src) {
    asm volatile("cp.async.cg.shared.global [%0], [%1], 16;" :: "r"(dst), "l"(src));
}
#define CPA_COMMIT()  asm volatile("cp.async.commit_group;" ::: "memory")
#define CPA_WAIT(n)   asm volatile("cp.async.wait_group %0;" :: "n"(n) : "memory")

// ---------------- mma.sync blade-plane GEMM core ----------------
constexpr int SKW = 40;
constexpr int ARR = 128 * SKW;
constexpr int STG = 2 * ARR;               // A, W per stage
constexpr int GEMM_SMEM = 2 * STG * (int)sizeof(f16);   // 40960 B

// Computes one 128x128 tile of A[blade] x W[grade]^T into acc.
DEVI void gemm_core(const f16* aP, const f16* wP, float acc[4][4][4],
                    f16* smem, uint32_t sb, int tid, int wm, int wn, int lane)
{
    const int lq = lane >> 3, lr = lane & 7;
    const uint32_t offA = (uint32_t)(((lq & 1) * 8 + lr) * SKW + (lq >> 1) * 8) * 2;
    const uint32_t offB = (uint32_t)(((lq >> 1) * 8 + lr) * SKW + (lq & 1) * 8) * 2;

    auto load_chunk = [&](int ch, int s) {
        const uint32_t base = sb + (uint32_t)(s * STG) * 2;
#pragma unroll
        for (int it = 0; it < 2; it++) {
            const int t = tid + it * 256;
            const int r = t >> 2, c = t & 3;
            const size_t src = (size_t)r * Csz + ch * 32 + c * 8;
            const uint32_t d = (uint32_t)(r * SKW + c * 8) * 2;
            cpa16(base + 0 * ARR * 2 + d, aP + src);
            cpa16(base + 1 * ARR * 2 + d, wP + src);
        }
        CPA_COMMIT();
    };

    load_chunk(0, 0);
    for (int ch = 0; ch < 8; ch++) {
        const int s = ch & 1;
        if (ch + 1 < 8) { load_chunk(ch + 1, (ch + 1) & 1); CPA_WAIT(1); }
        else            { CPA_WAIT(0); }
        __syncthreads();

        const uint32_t bA = sb + (uint32_t)(s * STG + 0 * ARR) * 2;
        const uint32_t bB = sb + (uint32_t)(s * STG + 1 * ARR) * 2;

#pragma unroll
        for (int kh = 0; kh < 2; kh++) {
            const uint32_t kb = (uint32_t)(kh * 16) * 2;
            uint32_t bh[4][2];
#pragma unroll
            for (int nb = 0; nb < 2; nb++) {
                const uint32_t nbase = (uint32_t)((wn * 32 + nb * 16) * SKW) * 2;
                ldsm_x4(bh[nb*2][0], bh[nb*2][1], bh[nb*2+1][0], bh[nb*2+1][1],
                        bB + nbase + offB + kb);
            }
#pragma unroll
            for (int mi = 0; mi < 4; mi++) {
                const uint32_t mbase = (uint32_t)((wm * 64 + mi * 16) * SKW) * 2;
                uint32_t a0, a1, a2, a3;
                ldsm_x4(a0, a1, a2, a3, bA + mbase + offA + kb);
#pragma unroll
                for (int ni = 0; ni < 4; ni++)
                    mma_f16(acc[mi][ni], a0, a1, a2, a3, bh[ni][0], bh[ni][1]);
            }
        }
        __syncthreads();
    }
}

// GEMM 1: fp32 output (feeds silu)
__global__ void __launch_bounds__(256, 2)
gemm_f32(const f16* __restrict__ A, const f16* __restrict__ W, float* __restrict__ OUT)
{
    extern __shared__ f16 smem[];
    const uint32_t sb = smem_u32(smem);
    const int tid = threadIdx.x, wid = tid >> 5, lane = tid & 31;
    const int blade = blockIdx.z, grade = GRc[blade];
    const int row0 = blockIdx.x * 128, col0 = blockIdx.y * 128;
    const int wm = wid & 1, wn = wid >> 1;

    float acc[4][4][4];
#pragma unroll
    for (int mi = 0; mi < 4; mi++)
#pragma unroll
        for (int ni = 0; ni < 4; ni++)
#pragma unroll
            for (int q = 0; q < 4; q++) acc[mi][ni][q] = 0.0f;

    gemm_core(A + (size_t)blade * BC + (size_t)row0 * Csz,
              W + (size_t)grade * Csz * Csz + (size_t)col0 * Csz,
              acc, smem, sb, tid, wm, wn, lane);

    float* outp = OUT + (size_t)blade * BC;
#pragma unroll
    for (int mi = 0; mi < 4; mi++) {
        const int m0 = row0 + wm * 64 + mi * 16 + (lane >> 2);
#pragma unroll
        for (int ni = 0; ni < 4; ni++) {
            const int n = col0 + wn * 32 + ni * 8 + (lane & 3) * 2;
            *(float2*)(outp + (size_t)m0 * Csz + n)       = make_float2(acc[mi][ni][0], acc[mi][ni][1]);
            *(float2*)(outp + (size_t)(m0 + 8) * Csz + n) = make_float2(acc[mi][ni][2], acc[mi][ni][3]);
        }
    }
}

// GEMM 2+3 merged: f16 output, z = blade + 8*outsel
__global__ void __launch_bounds__(256, 2)
gemm_dual_f16(const f16* __restrict__ A, const f16* __restrict__ WB,
              const f16* __restrict__ WC, f16* __restrict__ OB, f16* __restrict__ OC)
{
    extern __shared__ f16 smem[];
    const uint32_t sb = smem_u32(smem);
    const int tid = threadIdx.x, wid = tid >> 5, lane = tid & 31;
    const int z = blockIdx.z;
    const int blade = z & 7, outsel = z >> 3, grade = GRc[blade];
    const int row0 = blockIdx.x * 128, col0 = blockIdx.y * 128;
    const int wm = wid & 1, wn = wid >> 1;

    const f16* W = outsel ? WC : WB;
    f16* OUT     = outsel ? OC : OB;

    float acc[4][4][4];
#pragma unroll
    for (int mi = 0; mi < 4; mi++)
#pragma unroll
        for (int ni = 0; ni < 4; ni++)
#pragma unroll
            for (int q = 0; q < 4; q++) acc[mi][ni][q] = 0.0f;

    gemm_core(A + (size_t)blade * BC + (size_t)row0 * Csz,
              W + (size_t)grade * Csz * Csz + (size_t)col0 * Csz,
              acc, smem, sb, tid, wm, wn, lane);

    f16* outp = OUT + (size_t)blade * BC;
#pragma unroll
    for (int mi = 0; mi < 4; mi++) {
        const int m0 = row0 + wm * 64 + mi * 16 + (lane >> 2);
#pragma unroll
        for (int ni = 0; ni < 4; ni++) {
            const int n = col0 + wn * 32 + ni * 8 + (lane & 3) * 2;
            *(__half2*)(outp + (size_t)m0 * Csz + n) =
                __halves2half2(__float2half_rn(acc[mi][ni][0]), __float2half_rn(acc[mi][ni][1]));
            *(__half2*)(outp + (size_t)(m0 + 8) * Csz + n) =
                __halves2half2(__float2half_rn(acc[mi][ni][2]), __float2half_rn(acc[mi][ni][3]));
        }
    }
}

// ---------------- conversions & elementwise passes ----------------
__global__ void conv_x(const float* __restrict__ X, f16* __restrict__ H) {
    const size_t idx = (size_t)blockIdx.x * 256 + threadIdx.x;
    const float4 a = *(const float4*)(X + idx * 8);
    const float4 b = *(const float4*)(X + idx * 8 + 4);
    const float v[8] = {a.x, a.y, a.z, a.w, b.x, b.y, b.z, b.w};
#pragma unroll
    for (int k = 0; k < 8; k++) H[k * BC + idx] = __float2half_rn(v[k]);
}

// convert all three weight matrices for a layer in one launch
__global__ void conv_w3(const float* __restrict__ WA, const float* __restrict__ WB,
                        const float* __restrict__ WC,
                        f16* __restrict__ A, f16* __restrict__ B, f16* __restrict__ C) {
    const int idx = blockIdx.x * 256 + threadIdx.x;  // o*256+i
    const float4 va = *(const float4*)(WA + (size_t)idx * 4);
    const float4 vb = *(const float4*)(WB + (size_t)idx * 4);
    const float4 vc = *(const float4*)(WC + (size_t)idx * 4);
    A[0*65536+idx]=__float2half_rn(va.x); A[1*65536+idx]=__float2half_rn(va.y);
    A[2*65536+idx]=__float2half_rn(va.z); A[3*65536+idx]=__float2half_rn(va.w);
    B[0*65536+idx]=__float2half_rn(vb.x); B[1*65536+idx]=__float2half_rn(vb.y);
    B[2*65536+idx]=__float2half_rn(vb.z); B[3*65536+idx]=__float2half_rn(vb.w);
    C[0*65536+idx]=__float2half_rn(vc.x); C[1*65536+idx]=__float2half_rn(vc.y);
    C[2*65536+idx]=__float2half_rn(vc.z); C[3*65536+idx]=__float2half_rn(vc.w);
}

// silu: 1 elem/thread, fp32 raw in, f16 hi/lo out
__global__ void silu_pass(const float* __restrict__ RAW, const float* __restrict__ blin,
                          const float* __restrict__ pa, const float* __restrict__ pb,
                          f16* __restrict__ HH, f16* __restrict__ HL) {
    const size_t idx = (size_t)blockIdx.x * 256 + threadIdx.x;
    const int c = (int)(idx & 255);
    float y[8];
#pragma unroll
    for (int k = 0; k < 8; k++) y[k] = RAW[k * BC + idx];
    y[0] += blin[c];
    const float i0 = y[0];
    const float i1 = y[1]*y[1] + y[2]*y[2] + y[3]*y[3];
    const float i2 = y[4]*y[4] + y[5]*y[5] + y[6]*y[6];
    const float i3 = y[7]*y[7];
    const float g0 = sigm(pa[c*4+0] * i0 + pb[c*4+0]);
    const float g1 = sigm(pa[c*4+1] * i1 + pb[c*4+1]);
    const float g2 = sigm(pa[c*4+2] * i2 + pb[c*4+2]);
    const float g3 = sigm(pa[c*4+3] * i3 + pb[c*4+3]);
    const float gk[8] = {g0, g1, g1, g1, g2, g2, g2, g3};
#pragma unroll
    for (int k = 0; k < 8; k++) {
        const float v = y[k] * gk[k];
        const f16 h = __float2half_rn(v);
        HH[k * BC + idx] = h;
        HL[k * BC + idx] = __float2half_rn(v - __half2float(h));
    }
}

// ---------------- fused grade-norm + geometric product + layernorm ----------------
template <int OUTMODE>
__global__ void __launch_bounds__(256, 4)
gp_ln(const f16* __restrict__ XhH, const f16* __restrict__ XhL,
      const f16* __restrict__ XRraw, const f16* __restrict__ Lf,
      const float* __restrict__ NA, const float* __restrict__ GPW,
      const float* __restrict__ LNA, const float* __restrict__ BL,
      float* __restrict__ OutF, f16* __restrict__ OutH)
{
    const int b = blockIdx.x, c = threadIdx.x;
    const size_t idx = (size_t)b * Csz + c;

    float xv[8], rv[8], lv[8];
#pragma unroll
    for (int k = 0; k < 8; k++) {
        xv[k] = __half2float(XhH[k * BC + idx]) + __half2float(XhL[k * BC + idx]);
        rv[k] = __half2float(XRraw[k * BC + idx]);
        lv[k] = __half2float(Lf[k * BC + idx]);
    }
    lv[0] += BL[c];

    // grade_norm on rv (fused)
    {
        const float n0 = fabsf(rv[0]);
        const float n1 = sqrtf(rv[1]*rv[1] + rv[2]*rv[2] + rv[3]*rv[3]);
        const float n2 = sqrtf(rv[4]*rv[4] + rv[5]*rv[5] + rv[6]*rv[6]);
        const float n3 = fabsf(rv[7]);
        const float r0 = 1.0f / (fmaf(sigm(NA[c*4+0]), n0 - 1.0f, 1.0f) + 1e-6f);
        const float r1 = 1.0f / (fmaf(sigm(NA[c*4+1]), n1 - 1.0f, 1.0f) + 1e-6f);
        const float r2 = 1.0f / (fmaf(sigm(NA[c*4+2]), n2 - 1.0f, 1.0f) + 1e-6f);
        const float r3 = 1.0f / (fmaf(sigm(NA[c*4+3]), n3 - 1.0f, 1.0f) + 1e-6f);
        rv[0]*=r0; rv[1]*=r1; rv[2]*=r1; rv[3]*=r1;
        rv[4]*=r2; rv[5]*=r2; rv[6]*=r2; rv[7]*=r3;
    }

    float w20[20];
    {
        const float* wp = GPW + c * 20;
#pragma unroll
        for (int q = 0; q < 5; q++) *(float4*)&w20[q*4] = *(const float4*)(wp + q*4);
    }

    float gp[8] = {0,0,0,0,0,0,0,0};
#pragma unroll
    for (int i = 0; i < 8; i++) {
#pragma unroll
        for (int j = 0; j < 8; j++) {
            const int ma = ORD[i], mb = ORD[j];
            const int ko = IDXM[ma ^ mb];
            const int p  = PATHT[GRc[i]][GRc[j]][GRc[ko]];
            const bool neg = (NEGM[ma] >> mb) & 1;
            const float wv = neg ? -w20[p] : w20[p];
            gp[ko] = fmaf(wv, xv[i] * rv[j], gp[ko]);
        }
    }

    float s[8], sq = 0.0f;
#pragma unroll
    for (int k = 0; k < 8; k++) {
        s[k] = (lv[k] + gp[k]) * 0.70710678118654752f;
        sq = fmaf(s[k], s[k], sq);
    }
    float v = sqrtf(sq);

    __shared__ float red[8];
#pragma unroll
    for (int off = 16; off; off >>= 1) v += __shfl_xor_sync(0xffffffffu, v, off);
    if ((c & 31) == 0) red[c >> 5] = v;
    __syncthreads();
    const float tot = red[0]+red[1]+red[2]+red[3]+red[4]+red[5]+red[6]+red[7];
    const float scale = LNA[c] / (tot * (1.0f / 256.0f) + 1e-6f);

    if constexpr (OUTMODE == 0) {
#pragma unroll
        for (int k = 0; k < 8; k++)
            OutH[k * BC + idx] = __float2half_rn(s[k] * scale);
    } else {
        float4* dst = (float4*)(OutF + idx * 8);
        dst[0] = make_float4(s[0]*scale, s[1]*scale, s[2]*scale, s[3]*scale);
        dst[1] = make_float4(s[4]*scale, s[5]*scale, s[6]*scale, s[7]*scale);
    }
}

// ---------------- launch ----------------
extern "C" void kernel_launch(void* const* d_in, const int* in_sizes, int n_in,
                              void* d_out, int out_size)
{
    (void)in_sizes; (void)n_in; (void)out_size;
    const float* x = (const float*)d_in[0];
    float* out = (float*)d_out;

    cudaFuncSetAttribute(gemm_f32, cudaFuncAttributeMaxDynamicSharedMemorySize, GEMM_SMEM);
    cudaFuncSetAttribute(gemm_dual_f16, cudaFuncAttributeMaxDynamicSharedMemorySize, GEMM_SMEM);

    float* raw;
    f16 *xr, *lf, *inH, *hH, *hL, *wA, *wB, *wC;
    cudaGetSymbolAddress((void**)&raw, g_raw);
    cudaGetSymbolAddress((void**)&xr,  g_xr);
    cudaGetSymbolAddress((void**)&lf,  g_lf);
    cudaGetSymbolAddress((void**)&inH, g_inH);
    cudaGetSymbolAddress((void**)&hH,  g_hH);
    cudaGetSymbolAddress((void**)&hL,  g_hL);
    cudaGetSymbolAddress((void**)&wA,  g_wA);
    cudaGetSymbolAddress((void**)&wB,  g_wB);
    cudaGetSymbolAddress((void**)&wC,  g_wC);

    const int EB = (int)(BC / 256);
    const dim3 GG1(Bsz / 128, Csz / 128, NBl);       // 64 x 2 x 8
    const dim3 GG2(Bsz / 128, Csz / 128, 2 * NBl);   // 64 x 2 x 16 (xr + lf)

    conv_x<<<EB, 256>>>(x, inH);

    for (int l = 0; l < 2; l++) {
        const float* const* P = (const float* const*)(d_in + 1 + 10 * l);
        // P: [w_lin, b_lin, silu_a, silu_b, w_right, w_left, b_left, norm_a, gp_w, ln_a]
        conv_w3<<<256, 256>>>(P[0], P[4], P[5], wA, wB, wC);

        gemm_f32<<<GG1, 256, GEMM_SMEM>>>(inH, wA, raw);
        silu_pass<<<EB, 256>>>(raw, P[1], P[2], P[3], hH, hL);

        gemm_dual_f16<<<GG2, 256, GEMM_SMEM>>>(hH, wB, wC, xr, lf);

        if (l == 0)
            gp_ln<0><<<Bsz, 256>>>(hH, hL, xr, lf, P[7], P[8], P[9], P[6],
                                   nullptr, inH);
        else
            gp_ln<1><<<Bsz, 256>>>(hH, hL, xr, lf, P[7], P[8], P[9], P[6],
                                   out, nullptr);
    }
}

// round 17
// speedup vs baseline: 1.6157x; 1.0102x over previous
#include <cuda_runtime.h>
#include <cuda_fp16.h>
#include <cstdint>
#include <cstddef>

#define DEVI __device__ __forceinline__
typedef __half f16;

constexpr int Bsz = 8192, Csz = 256, NBl = 8;
constexpr size_t BC = (size_t)Bsz * Csz;   // elems per blade plane

// ---------------- scratch (device globals) ----------------
__device__ f16 g_raw[NBl * BC];   // w_lin gemm output (f16)
__device__ f16 g_xr [NBl * BC];   // w_right gemm output (f16, pre-gradenorm)
__device__ f16 g_lf [NBl * BC];   // w_left gemm output (f16)
__device__ f16 g_inH[NBl * BC];   // layer input (fp16)
__device__ f16 g_hH [NBl * BC];   // h hi/lo (fp16 pair, for exact gp_ln reconstruction)
__device__ f16 g_hL [NBl * BC];
__device__ f16 g_wA [4 * Csz * Csz];   // w_lin (f16)
__device__ f16 g_wB [4 * Csz * Csz];   // w_right
__device__ f16 g_wC [4 * Csz * Csz];   // w_left

// ---------------- algebra tables ----------------
__device__ constexpr int ORD [8] = {0, 1, 2, 4, 3, 5, 6, 7};
__device__ constexpr int IDXM[8] = {0, 1, 2, 4, 3, 5, 6, 7};
__device__ constexpr int GRc [8] = {0, 1, 1, 1, 2, 2, 2, 3};
__device__ constexpr unsigned NEGM[8] = {0x00u, 0x00u, 0xAAu, 0xAAu,
                                         0x66u, 0x66u, 0xCCu, 0xCCu};
__device__ constexpr signed char PATHT[4][4][4] = {
  { { 0,-1,-1,-1}, {-1, 1,-1,-1}, {-1,-1, 2,-1}, {-1,-1,-1, 3} },
  { {-1, 4,-1,-1}, { 5,-1, 6,-1}, {-1, 7,-1, 8}, {-1,-1, 9,-1} },
  { {-1,-1,10,-1}, {-1,11,-1,12}, {13,-1,14,-1}, {-1,15,-1,-1} },
  { {-1,-1,-1,16}, {-1,-1,17,-1}, {-1,18,-1,-1}, {19,-1,-1,-1} }
};

DEVI float sigm(float x) { return 1.0f / (1.0f + __expf(-x)); }

DEVI uint32_t smem_u32(const void* p) {
    uint32_t a;
    asm("{ .reg .u64 t; cvta.to.shared.u64 t, %1; cvt.u32.u64 %0, t; }" : "=r"(a) : "l"(p));
    return a;
}

// ---- warp MMA primitives ----
DEVI void ldsm_x4(uint32_t& r0, uint32_t& r1, uint32_t& r2, uint32_t& r3, uint32_t addr) {
    asm volatile("ldmatrix.sync.aligned.m8n8.x4.shared.b16 {%0,%1,%2,%3}, [%4];"
                 : "=r"(r0), "=r"(r1), "=r"(r2), "=r"(r3) : "r"(addr));
}
DEVI void mma_f16(float* c, uint32_t a0, uint32_t a1, uint32_t a2, uint32_t a3,
                  uint32_t b0, uint32_t b1) {
    asm volatile(
        "mma.sync.aligned.m16n8k16.row.col.f32.f16.f16.f32 "
        "{%0,%1,%2,%3}, {%4,%5,%6,%7}, {%8,%9}, {%0,%1,%2,%3};"
        : "+f"(c[0]), "+f"(c[1]), "+f"(c[2]), "+f"(c[3])
        : "r"(a0), "r"(a1), "r"(a2), "r"(a3), "r"(b0), "r"(b1));
}
DEVI void cpa16(uint32_t dst, const void* src) {
    asm volatile("cp.async.cg.shared.global [%0], [%1], 16;" :: "r"(dst), "l"(src));
}
#define CPA_COMMIT()  asm volatile("cp.async.commit_group;" ::: "memory")
#define CPA_WAIT(n)   asm volatile("cp.async.wait_group %0;" :: "n"(n) : "memory")

// ---------------- mma.sync blade-plane GEMM core ----------------
constexpr int SKW = 40;
constexpr int ARR = 128 * SKW;
constexpr int STG = 2 * ARR;               // A, W per stage
constexpr int GEMM_SMEM = 2 * STG * (int)sizeof(f16);   // 40960 B

DEVI void gemm_core(const f16* aP, const f16* wP, float acc[4][4][4],
                    f16* smem, uint32_t sb, int tid, int wm, int wn, int lane)
{
    const int lq = lane >> 3, lr = lane & 7;
    const uint32_t offA = (uint32_t)(((lq & 1) * 8 + lr) * SKW + (lq >> 1) * 8) * 2;
    const uint32_t offB = (uint32_t)(((lq >> 1) * 8 + lr) * SKW + (lq & 1) * 8) * 2;

    auto load_chunk = [&](int ch, int s) {
        const uint32_t base = sb + (uint32_t)(s * STG) * 2;
#pragma unroll
        for (int it = 0; it < 2; it++) {
            const int t = tid + it * 256;
            const int r = t >> 2, c = t & 3;
            const size_t src = (size_t)r * Csz + ch * 32 + c * 8;
            const uint32_t d = (uint32_t)(r * SKW + c * 8) * 2;
            cpa16(base + 0 * ARR * 2 + d, aP + src);
            cpa16(base + 1 * ARR * 2 + d, wP + src);
        }
        CPA_COMMIT();
    };

    load_chunk(0, 0);
    for (int ch = 0; ch < 8; ch++) {
        const int s = ch & 1;
        if (ch + 1 < 8) { load_chunk(ch + 1, (ch + 1) & 1); CPA_WAIT(1); }
        else            { CPA_WAIT(0); }
        __syncthreads();

        const uint32_t bA = sb + (uint32_t)(s * STG + 0 * ARR) * 2;
        const uint32_t bB = sb + (uint32_t)(s * STG + 1 * ARR) * 2;

#pragma unroll
        for (int kh = 0; kh < 2; kh++) {
            const uint32_t kb = (uint32_t)(kh * 16) * 2;
            uint32_t bh[4][2];
#pragma unroll
            for (int nb = 0; nb < 2; nb++) {
                const uint32_t nbase = (uint32_t)((wn * 32 + nb * 16) * SKW) * 2;
                ldsm_x4(bh[nb*2][0], bh[nb*2][1], bh[nb*2+1][0], bh[nb*2+1][1],
                        bB + nbase + offB + kb);
            }
#pragma unroll
            for (int mi = 0; mi < 4; mi++) {
                const uint32_t mbase = (uint32_t)((wm * 64 + mi * 16) * SKW) * 2;
                uint32_t a0, a1, a2, a3;
                ldsm_x4(a0, a1, a2, a3, bA + mbase + offA + kb);
#pragma unroll
                for (int ni = 0; ni < 4; ni++)
                    mma_f16(acc[mi][ni], a0, a1, a2, a3, bh[ni][0], bh[ni][1]);
            }
        }
        __syncthreads();
    }
}

// f16 epilogue writer (half2 stores, same instruction count as fp32 float2)
DEVI void epi_f16(f16* outp, float acc[4][4][4], int row0, int col0,
                  int wm, int wn, int lane)
{
#pragma unroll
    for (int mi = 0; mi < 4; mi++) {
        const int m0 = row0 + wm * 64 + mi * 16 + (lane >> 2);
#pragma unroll
        for (int ni = 0; ni < 4; ni++) {
            const int n = col0 + wn * 32 + ni * 8 + (lane & 3) * 2;
            *(__half2*)(outp + (size_t)m0 * Csz + n) =
                __halves2half2(__float2half_rn(acc[mi][ni][0]), __float2half_rn(acc[mi][ni][1]));
            *(__half2*)(outp + (size_t)(m0 + 8) * Csz + n) =
                __halves2half2(__float2half_rn(acc[mi][ni][2]), __float2half_rn(acc[mi][ni][3]));
        }
    }
}

// GEMM 1: f16 output (feeds silu)
__global__ void __launch_bounds__(256, 2)
gemm_one(const f16* __restrict__ A, const f16* __restrict__ W, f16* __restrict__ OUT)
{
    extern __shared__ f16 smem[];
    const uint32_t sb = smem_u32(smem);
    const int tid = threadIdx.x, wid = tid >> 5, lane = tid & 31;
    const int blade = blockIdx.z, grade = GRc[blade];
    const int row0 = blockIdx.x * 128, col0 = blockIdx.y * 128;
    const int wm = wid & 1, wn = wid >> 1;

    float acc[4][4][4];
#pragma unroll
    for (int mi = 0; mi < 4; mi++)
#pragma unroll
        for (int ni = 0; ni < 4; ni++)
#pragma unroll
            for (int q = 0; q < 4; q++) acc[mi][ni][q] = 0.0f;

    gemm_core(A + (size_t)blade * BC + (size_t)row0 * Csz,
              W + (size_t)grade * Csz * Csz + (size_t)col0 * Csz,
              acc, smem, sb, tid, wm, wn, lane);

    epi_f16(OUT + (size_t)blade * BC, acc, row0, col0, wm, wn, lane);
}

// GEMM 2+3 merged: f16 output, z = blade + 8*outsel
__global__ void __launch_bounds__(256, 2)
gemm_dual_f16(const f16* __restrict__ A, const f16* __restrict__ WB,
              const f16* __restrict__ WC, f16* __restrict__ OB, f16* __restrict__ OC)
{
    extern __shared__ f16 smem[];
    const uint32_t sb = smem_u32(smem);
    const int tid = threadIdx.x, wid = tid >> 5, lane = tid & 31;
    const int z = blockIdx.z;
    const int blade = z & 7, outsel = z >> 3, grade = GRc[blade];
    const int row0 = blockIdx.x * 128, col0 = blockIdx.y * 128;
    const int wm = wid & 1, wn = wid >> 1;

    const f16* W = outsel ? WC : WB;
    f16* OUT     = outsel ? OC : OB;

    float acc[4][4][4];
#pragma unroll
    for (int mi = 0; mi < 4; mi++)
#pragma unroll
        for (int ni = 0; ni < 4; ni++)
#pragma unroll
            for (int q = 0; q < 4; q++) acc[mi][ni][q] = 0.0f;

    gemm_core(A + (size_t)blade * BC + (size_t)row0 * Csz,
              W + (size_t)grade * Csz * Csz + (size_t)col0 * Csz,
              acc, smem, sb, tid, wm, wn, lane);

    epi_f16(OUT + (size_t)blade * BC, acc, row0, col0, wm, wn, lane);
}

// ---------------- conversions & elementwise passes ----------------
__global__ void conv_x(const float* __restrict__ X, f16* __restrict__ H) {
    const size_t idx = (size_t)blockIdx.x * 256 + threadIdx.x;
    const float4 a = *(const float4*)(X + idx * 8);
    const float4 b = *(const float4*)(X + idx * 8 + 4);
    const float v[8] = {a.x, a.y, a.z, a.w, b.x, b.y, b.z, b.w};
#pragma unroll
    for (int k = 0; k < 8; k++) H[k * BC + idx] = __float2half_rn(v[k]);
}

__global__ void conv_w3(const float* __restrict__ WA, const float* __restrict__ WB,
                        const float* __restrict__ WC,
                        f16* __restrict__ A, f16* __restrict__ B, f16* __restrict__ C) {
    const int idx = blockIdx.x * 256 + threadIdx.x;  // o*256+i
    const float4 va = *(const float4*)(WA + (size_t)idx * 4);
    const float4 vb = *(const float4*)(WB + (size_t)idx * 4);
    const float4 vc = *(const float4*)(WC + (size_t)idx * 4);
    A[0*65536+idx]=__float2half_rn(va.x); A[1*65536+idx]=__float2half_rn(va.y);
    A[2*65536+idx]=__float2half_rn(va.z); A[3*65536+idx]=__float2half_rn(va.w);
    B[0*65536+idx]=__float2half_rn(vb.x); B[1*65536+idx]=__float2half_rn(vb.y);
    B[2*65536+idx]=__float2half_rn(vb.z); B[3*65536+idx]=__float2half_rn(vb.w);
    C[0*65536+idx]=__float2half_rn(vc.x); C[1*65536+idx]=__float2half_rn(vc.y);
    C[2*65536+idx]=__float2half_rn(vc.z); C[3*65536+idx]=__float2half_rn(vc.w);
}

// silu: 1 elem/thread, f16 raw in, f16 hi/lo out
__global__ void silu_pass(const f16* __restrict__ RAW, const float* __restrict__ blin,
                          const float* __restrict__ pa, const float* __restrict__ pb,
                          f16* __restrict__ HH, f16* __restrict__ HL) {
    const size_t idx = (size_t)blockIdx.x * 256 + threadIdx.x;
    const int c = (int)(idx & 255);
    float y[8];
#pragma unroll
    for (int k = 0; k < 8; k++) y[k] = __half2float(RAW[k * BC + idx]);
    y[0] += blin[c];
    const float i0 = y[0];
    const float i1 = y[1]*y[1] + y[2]*y[2] + y[3]*y[3];
    const float i2 = y[4]*y[4] + y[5]*y[5] + y[6]*y[6];
    const float i3 = y[7]*y[7];
    const float g0 = sigm(pa[c*4+0] * i0 + pb[c*4+0]);
    const float g1 = sigm(pa[c*4+1] * i1 + pb[c*4+1]);
    const float g2 = sigm(pa[c*4+2] * i2 + pb[c*4+2]);
    const float g3 = sigm(pa[c*4+3] * i3 + pb[c*4+3]);
    const float gk[8] = {g0, g1, g1, g1, g2, g2, g2, g3};
#pragma unroll
    for (int k = 0; k < 8; k++) {
        const float v = y[k] * gk[k];
        const f16 h = __float2half_rn(v);
        HH[k * BC + idx] = h;
        HL[k * BC + idx] = __float2half_rn(v - __half2float(h));
    }
}

// ---------------- fused grade-norm + geometric product + layernorm ----------------
template <int OUTMODE>
__global__ void __launch_bounds__(256, 4)
gp_ln(const f16* __restrict__ XhH, const f16* __restrict__ XhL,
      const f16* __restrict__ XRraw, const f16* __restrict__ Lf,
      const float* __restrict__ NA, const float* __restrict__ GPW,
      const float* __restrict__ LNA, const float* __restrict__ BL,
      float* __restrict__ OutF, f16* __restrict__ OutH)
{
    const int b = blockIdx.x, c = threadIdx.x;
    const size_t idx = (size_t)b * Csz + c;

    float xv[8], rv[8], lv[8];
#pragma unroll
    for (int k = 0; k < 8; k++) {
        xv[k] = __half2float(XhH[k * BC + idx]) + __half2float(XhL[k * BC + idx]);
        rv[k] = __half2float(XRraw[k * BC + idx]);
        lv[k] = __half2float(Lf[k * BC + idx]);
    }
    lv[0] += BL[c];

    // grade_norm on rv (fused)
    {
        const float n0 = fabsf(rv[0]);
        const float n1 = sqrtf(rv[1]*rv[1] + rv[2]*rv[2] + rv[3]*rv[3]);
        const float n2 = sqrtf(rv[4]*rv[4] + rv[5]*rv[5] + rv[6]*rv[6]);
        const float n3 = fabsf(rv[7]);
        const float r0 = 1.0f / (fmaf(sigm(NA[c*4+0]), n0 - 1.0f, 1.0f) + 1e-6f);
        const float r1 = 1.0f / (fmaf(sigm(NA[c*4+1]), n1 - 1.0f, 1.0f) + 1e-6f);
        const float r2 = 1.0f / (fmaf(sigm(NA[c*4+2]), n2 - 1.0f, 1.0f) + 1e-6f);
        const float r3 = 1.0f / (fmaf(sigm(NA[c*4+3]), n3 - 1.0f, 1.0f) + 1e-6f);
        rv[0]*=r0; rv[1]*=r1; rv[2]*=r1; rv[3]*=r1;
        rv[4]*=r2; rv[5]*=r2; rv[6]*=r2; rv[7]*=r3;
    }

    float w20[20];
    {
        const float* wp = GPW + c * 20;
#pragma unroll
        for (int q = 0; q < 5; q++) *(float4*)&w20[q*4] = *(const float4*)(wp + q*4);
    }

    float gp[8] = {0,0,0,0,0,0,0,0};
#pragma unroll
    for (int i = 0; i < 8; i++) {
#pragma unroll
        for (int j = 0; j < 8; j++) {
            const int ma = ORD[i], mb = ORD[j];
            const int ko = IDXM[ma ^ mb];
            const int p  = PATHT[GRc[i]][GRc[j]][GRc[ko]];
            const bool neg = (NEGM[ma] >> mb) & 1;
            const float wv = neg ? -w20[p] : w20[p];
            gp[ko] = fmaf(wv, xv[i] * rv[j], gp[ko]);
        }
    }

    float s[8], sq = 0.0f;
#pragma unroll
    for (int k = 0; k < 8; k++) {
        s[k] = (lv[k] + gp[k]) * 0.70710678118654752f;
        sq = fmaf(s[k], s[k], sq);
    }
    float v = sqrtf(sq);

    __shared__ float red[8];
#pragma unroll
    for (int off = 16; off; off >>= 1) v += __shfl_xor_sync(0xffffffffu, v, off);
    if ((c & 31) == 0) red[c >> 5] = v;
    __syncthreads();
    const float tot = red[0]+red[1]+red[2]+red[3]+red[4]+red[5]+red[6]+red[7];
    const float scale = LNA[c] / (tot * (1.0f / 256.0f) + 1e-6f);

    if constexpr (OUTMODE == 0) {
#pragma unroll
        for (int k = 0; k < 8; k++)
            OutH[k * BC + idx] = __float2half_rn(s[k] * scale);
    } else {
        float4* dst = (float4*)(OutF + idx * 8);
        dst[0] = make_float4(s[0]*scale, s[1]*scale, s[2]*scale, s[3]*scale);
        dst[1] = make_float4(s[4]*scale, s[5]*scale, s[6]*scale, s[7]*scale);
    }
}

// ---------------- launch ----------------
extern "C" void kernel_launch(void* const* d_in, const int* in_sizes, int n_in,
                              void* d_out, int out_size)
{
    (void)in_sizes; (void)n_in; (void)out_size;
    const float* x = (const float*)d_in[0];
    float* out = (float*)d_out;

    cudaFuncSetAttribute(gemm_one, cudaFuncAttributeMaxDynamicSharedMemorySize, GEMM_SMEM);
    cudaFuncSetAttribute(gemm_dual_f16, cudaFuncAttributeMaxDynamicSharedMemorySize, GEMM_SMEM);

    f16 *raw, *xr, *lf, *inH, *hH, *hL, *wA, *wB, *wC;
    cudaGetSymbolAddress((void**)&raw, g_raw);
    cudaGetSymbolAddress((void**)&xr,  g_xr);
    cudaGetSymbolAddress((void**)&lf,  g_lf);
    cudaGetSymbolAddress((void**)&inH, g_inH);
    cudaGetSymbolAddress((void**)&hH,  g_hH);
    cudaGetSymbolAddress((void**)&hL,  g_hL);
    cudaGetSymbolAddress((void**)&wA,  g_wA);
    cudaGetSymbolAddress((void**)&wB,  g_wB);
    cudaGetSymbolAddress((void**)&wC,  g_wC);

    const int EB = (int)(BC / 256);
    const dim3 GG1(Bsz / 128, Csz / 128, NBl);       // 64 x 2 x 8
    const dim3 GG2(Bsz / 128, Csz / 128, 2 * NBl);   // 64 x 2 x 16 (xr + lf)

    conv_x<<<EB, 256>>>(x, inH);

    for (int l = 0; l < 2; l++) {
        const float* const* P = (const float* const*)(d_in + 1 + 10 * l);
        // P: [w_lin, b_lin, silu_a, silu_b, w_right, w_left, b_left, norm_a, gp_w, ln_a]
        conv_w3<<<256, 256>>>(P[0], P[4], P[5], wA, wB, wC);

        gemm_one<<<GG1, 256, GEMM_SMEM>>>(inH, wA, raw);
        silu_pass<<<EB, 256>>>(raw, P[1], P[2], P[3], hH, hL);

        gemm_dual_f16<<<GG2, 256, GEMM_SMEM>>>(hH, wB, wC, xr, lf);

        if (l == 0)
            gp_ln<0><<<Bsz, 256>>>(hH, hL, xr, lf, P[7], P[8], P[9], P[6],
                                   nullptr, inH);
        else
            gp_ln<1><<<Bsz, 256>>>(hH, hL, xr, lf, P[7], P[8], P[9], P[6],
                                   out, nullptr);
    }
}